// round 12
// baseline (speedup 1.0000x reference)
#include <cuda_runtime.h>
#include <cuda_fp16.h>
#include <cstdint>

// ---------------------------------------------------------------------------
// FP8Linear: out[M,N] = x[M,K] @ (qweight*scales)^T + bias
// M=8192, N=16384, K=4096, group=128.
// R12: GEMM = exact R10 (persistent grid=304, CTA 128x128, 4 warps, 64x64
// warp tile, TK=32, 4 stages, wait_group 2, cross-tile load cursor; measured
// 2083.9us twice). Prep: prep_x + prep_w merged into ONE kernel so the two
// DRAM-bound phases share a wave instead of serializing (R11's in-GEMM fusion
// reverted: phase-specialized shapes win).
// ---------------------------------------------------------------------------

#define M_ALL 8192
#define N_ALL 16384
#define K_ALL 4096
#define TM 128
#define TN 128
#define TK 32
#define THREADS 128
#define NKT (K_ALL / TK)              // 128
#define NSTAGES 4
#define STAGE_BYTES 16384             // A 8KB + B 8KB (fp16)
#define SMEM_TOTAL (NSTAGES * STAGE_BYTES)  // 65536
#define NTILES 8192
#define GRID 304                      // 2 CTAs x 152 SMs

#define X_CHUNKS 4194304u             // 2^22
#define W_CHUNKS 8388608u             // 2^23

// Packed operand scratch (fragment-major, fp16) -- layout unchanged since R4.
// A' chunk (mb,kt,it,s,lane): regs x/y/z/w = {m=g,k0},{m=g+8,k0},{m=g,k0+8},{m=g+8,k0+8}
//   chunk id = mb*65536 + kt*512 + it*64 + s*32 + lane
// B' chunk (nb,kt,jt,lane):   regs x/y/z/w = (s0,r0),(s0,r1),(s1,r0),(s1,r1)
//   chunk id = nb*65536 + kt*512 + jt*32 + lane
__device__ uint4 Xp[64ull * 128 * 8 * 2 * 32];     //  64 MB
__device__ uint4 Wp[128ull * 128 * 16 * 32];       // 128 MB

// ---------------- helpers ----------------
__device__ __forceinline__ void cp_async16(uint32_t smem_dst, const void* gsrc) {
    asm volatile("cp.async.cg.shared.global [%0], [%1], 16;"
                 :: "r"(smem_dst), "l"(__cvta_generic_to_global(gsrc))
                 : "memory");
}
#define CP_COMMIT() asm volatile("cp.async.commit_group;" ::: "memory")
#define CP_WAIT2()  asm volatile("cp.async.wait_group 2;" ::: "memory")

__device__ __forceinline__ void mma_f16(float* c, const uint32_t* a,
                                        uint32_t b0, uint32_t b1) {
    asm volatile(
        "mma.sync.aligned.m16n8k16.row.col.f32.f16.f16.f32 "
        "{%0,%1,%2,%3}, {%4,%5,%6,%7}, {%8,%9}, {%0,%1,%2,%3};"
        : "+f"(c[0]), "+f"(c[1]), "+f"(c[2]), "+f"(c[3])
        : "r"(a[0]), "r"(a[1]), "r"(a[2]), "r"(a[3]), "r"(b0), "r"(b1));
}

__device__ __forceinline__ uint32_t h2(float lo, float hi) {
    __half2 h = __floats2half2_rn(lo, hi);
    return *(uint32_t*)&h;
}

// tile pid -> tile coords (GROUP_M=16 rasterization, unchanged)
__device__ __forceinline__ void tile_coords(int pid, int* pm, int* pn) {
    int group = pid >> 11;
    int loc = pid & 2047;
    *pm = group * 16 + (loc & 15);
    *pn = loc >> 4;
}

// ---------------- merged prep kernel ----------------
// gid < X_CHUNKS: Xp chunk; else Wp chunk (gid - X_CHUNKS).
// X cid fields: lane[0:5) s[5] it[6:9) kt[9:16) mb[16:22)
// W cid fields: lane[0:5) jt[5:9) kt[9:16) nb[16:23)
__global__ void __launch_bounds__(256)
prep_all_kernel(const float* __restrict__ X,
                const float* __restrict__ W,
                const float* __restrict__ S) {
    uint32_t gid = blockIdx.x * 256 + threadIdx.x;
    if (gid < X_CHUNKS) {
        uint32_t cid = gid;
        int lane = cid & 31;
        int s    = (cid >> 5) & 1;
        int it   = (cid >> 6) & 7;
        int kt   = (cid >> 9) & 127;
        int mb   = cid >> 16;
        int g = lane >> 2, tig = lane & 3;
        int m0 = mb * 128 + it * 16 + g;
        int k0 = kt * 32 + s * 16 + 2 * tig;
        const float* p0 = X + (size_t)m0 * K_ALL + k0;
        const float* p1 = X + (size_t)(m0 + 8) * K_ALL + k0;
        float2 v0 = *(const float2*)(p0);
        float2 v1 = *(const float2*)(p1);
        float2 v2 = *(const float2*)(p0 + 8);
        float2 v3 = *(const float2*)(p1 + 8);
        uint4 o;
        o.x = h2(v0.x, v0.y);
        o.y = h2(v1.x, v1.y);
        o.z = h2(v2.x, v2.y);
        o.w = h2(v3.x, v3.y);
        Xp[cid] = o;
    } else {
        uint32_t cid = gid - X_CHUNKS;
        int lane = cid & 31;
        int jt   = (cid >> 5) & 15;
        int kt   = (cid >> 9) & 127;
        int nb   = cid >> 16;
        int g = lane >> 2, tig = lane & 3;
        int n  = nb * 128 + jt * 8 + g;
        int kb = kt * 32 + 2 * tig;
        float sc = __ldg(S + (size_t)n * 32 + (kt >> 2));
        const float* p = W + (size_t)n * K_ALL + kb;
        float2 v0 = *(const float2*)(p);
        float2 v1 = *(const float2*)(p + 8);
        float2 v2 = *(const float2*)(p + 16);
        float2 v3 = *(const float2*)(p + 24);
        uint4 o;
        o.x = h2(v0.x * sc, v0.y * sc);
        o.y = h2(v1.x * sc, v1.y * sc);
        o.z = h2(v2.x * sc, v2.y * sc);
        o.w = h2(v3.x * sc, v3.y * sc);
        Wp[cid] = o;
    }
}

// ---------------- GEMM (exact R10) ----------------
extern __shared__ __align__(1024) char smem_raw[];

__device__ __forceinline__ void load_tile(const uint4* __restrict__ Ablk,
                                          const uint4* __restrict__ Bblk,
                                          char* stage, int tid) {
    uint32_t sb = (uint32_t)__cvta_generic_to_shared(stage);
    #pragma unroll
    for (int i = 0; i < 4; i++)
        cp_async16(sb + (tid + i * THREADS) * 16, Ablk + tid + i * THREADS);
    #pragma unroll
    for (int i = 0; i < 4; i++)
        cp_async16(sb + (tid + (4 + i) * THREADS) * 16, Bblk + tid + i * THREADS);
}

__global__ void __launch_bounds__(THREADS, 2)
fp8linear_hmma_kernel(const float* __restrict__ BIAS,
                      float* __restrict__ OUT) {
    const int tid = threadIdx.x;
    const int lane = tid & 31;
    const int wid = tid >> 5;      // 0..3
    const int wm = wid & 1;        // 2 x 64 rows
    const int wn = wid >> 1;       // 2 x 64 cols (8 n8-tiles)
    const int g = lane >> 2;
    const int tig = lane & 3;

    // ---- load cursor (runs 3 k-steps ahead, across tiles) ----
    int ltile = blockIdx.x;
    int lkt = 0;
    int lm, ln;
    tile_coords(ltile, &lm, &ln);
    const uint4* Al = Xp + (size_t)lm * 65536;
    const uint4* Bl = Wp + (size_t)ln * 65536;

    // prologue: stages 0..2 (lkt 0..2 of first tile)
    #pragma unroll
    for (int p = 0; p < 3; p++) {
        load_tile(Al + lkt * 512, Bl + lkt * 512,
                  smem_raw + p * STAGE_BYTES, tid);
        CP_COMMIT();
        lkt++;
    }

    float acc[4][8][4];

    for (int ptile = blockIdx.x; ptile < NTILES; ptile += GRID) {
        int pid_m, pid_n;
        tile_coords(ptile, &pid_m, &pid_n);

        #pragma unroll
        for (int i = 0; i < 4; i++)
            #pragma unroll
            for (int j = 0; j < 8; j++)
                #pragma unroll
                for (int q = 0; q < 4; q++) acc[i][j][q] = 0.0f;

        for (int kt = 0; kt < NKT; kt++) {
            CP_WAIT2();
            __syncthreads();

            // produce: step kt+3 of the load stream (rolls into next tile)
            if (lkt == NKT) {
                lkt = 0;
                ltile += GRID;
                if (ltile < NTILES) {
                    tile_coords(ltile, &lm, &ln);
                    Al = Xp + (size_t)lm * 65536;
                    Bl = Wp + (size_t)ln * 65536;
                }
            }
            if (ltile < NTILES)
                load_tile(Al + lkt * 512, Bl + lkt * 512,
                          smem_raw + ((kt + 3) & 3) * STAGE_BYTES, tid);
            CP_COMMIT();
            lkt++;

            // consume stage kt&3
            const char* stg = smem_raw + (kt & 3) * STAGE_BYTES;
            const uint4* As = (const uint4*)stg;
            const uint4* Bs = (const uint4*)(stg + 8192);

            uint4 bfr[8];
            #pragma unroll
            for (int j = 0; j < 8; j++)
                bfr[j] = Bs[(wn * 8 + j) * 32 + lane];

            #pragma unroll
            for (int s = 0; s < 2; s++) {
                uint4 afr[4];
                #pragma unroll
                for (int i = 0; i < 4; i++)
                    afr[i] = As[((wm * 4 + i) * 2 + s) * 32 + lane];
                #pragma unroll
                for (int i = 0; i < 4; i++) {
                    #pragma unroll
                    for (int j = 0; j < 8; j++) {
                        uint32_t b0 = s ? bfr[j].z : bfr[j].x;
                        uint32_t b1 = s ? bfr[j].w : bfr[j].y;
                        mma_f16(acc[i][j], (const uint32_t*)&afr[i], b0, b1);
                    }
                }
            }
        }

        // ---- epilogue (overlaps next tile's in-flight prologue loads) ----
        #pragma unroll
        for (int j = 0; j < 8; j++) {
            int col = pid_n * TN + wn * 64 + j * 8 + tig * 2;
            float2 bb = *(const float2*)(BIAS + col);
            #pragma unroll
            for (int i = 0; i < 4; i++) {
                int row0 = pid_m * TM + wm * 64 + i * 16 + g;
                float2 o0, o1;
                o0.x = acc[i][j][0] + bb.x;
                o0.y = acc[i][j][1] + bb.y;
                o1.x = acc[i][j][2] + bb.x;
                o1.y = acc[i][j][3] + bb.y;
                *(float2*)(OUT + (size_t)row0 * N_ALL + col) = o0;
                *(float2*)(OUT + (size_t)(row0 + 8) * N_ALL + col) = o1;
            }
        }
    }
}

// ---------------- launch ----------------
extern "C" void kernel_launch(void* const* d_in, const int* in_sizes, int n_in,
                              void* d_out, int out_size) {
    const float* x = (const float*)d_in[0];      // [4,2048,4096]
    const float* qw = (const float*)d_in[1];     // [16384,4096]
    const float* sc = (const float*)d_in[2];     // [16384,32]
    const float* bias = (const float*)d_in[3];   // [16384]
    float* out = (float*)d_out;                  // [4,2048,16384]

    prep_all_kernel<<<(X_CHUNKS + W_CHUNKS) / 256, 256>>>(x, qw, sc);

    cudaFuncSetAttribute(fp8linear_hmma_kernel,
                         cudaFuncAttributeMaxDynamicSharedMemorySize, SMEM_TOTAL);
    fp8linear_hmma_kernel<<<GRID, THREADS, SMEM_TOTAL>>>(bias, out);
}

// round 15
// speedup vs baseline: 1.5535x; 1.5535x over previous
#include <cuda_runtime.h>
#include <cuda_fp16.h>
#include <cstdint>

// ---------------------------------------------------------------------------
// FP8Linear: out[M,N] = x[M,K] @ (qweight*scales)^T + bias
// M=8192, N=16384, K=4096, group=128.
// R13: exact R10 resubmission (control). R12 ran the byte-identical GEMM 58%
// slower with cycle-accounting that implies a ~35% SM clock drop (DVFS), so
// this round disambiguates environment drift from the merged-prep change.
// Structure: separate prep_x/prep_w kernels (fragment-pack fp16, scale folded
// into W), then persistent GEMM grid=304: CTA 128x128, 4 warps, 64x64 warp
// tile, TK=32, 4x16KB stages, wait_group 2, cross-tile load cursor.
// ---------------------------------------------------------------------------

#define M_ALL 8192
#define N_ALL 16384
#define K_ALL 4096
#define TM 128
#define TN 128
#define TK 32
#define THREADS 128
#define NKT (K_ALL / TK)              // 128
#define NSTAGES 4
#define STAGE_BYTES 16384             // A 8KB + B 8KB (fp16)
#define SMEM_TOTAL (NSTAGES * STAGE_BYTES)  // 65536
#define NTILES 8192
#define GRID 304                      // 2 CTAs x 152 SMs

// Packed operand scratch (fragment-major, fp16) -- layout unchanged since R4.
// A' chunk (mb,kt,it,s,lane): regs x/y/z/w = {m=g,k0},{m=g+8,k0},{m=g,k0+8},{m=g+8,k0+8}
//   chunk id = mb*65536 + kt*512 + it*64 + s*32 + lane
// B' chunk (nb,kt,jt,lane):   regs x/y/z/w = (s0,r0),(s0,r1),(s1,r0),(s1,r1)
//   chunk id = nb*65536 + kt*512 + jt*32 + lane
__device__ uint4 Xp[64ull * 128 * 8 * 2 * 32];     //  64 MB
__device__ uint4 Wp[128ull * 128 * 16 * 32];       // 128 MB

// ---------------- helpers ----------------
__device__ __forceinline__ void cp_async16(uint32_t smem_dst, const void* gsrc) {
    asm volatile("cp.async.cg.shared.global [%0], [%1], 16;"
                 :: "r"(smem_dst), "l"(__cvta_generic_to_global(gsrc))
                 : "memory");
}
#define CP_COMMIT() asm volatile("cp.async.commit_group;" ::: "memory")
#define CP_WAIT2()  asm volatile("cp.async.wait_group 2;" ::: "memory")

__device__ __forceinline__ void mma_f16(float* c, const uint32_t* a,
                                        uint32_t b0, uint32_t b1) {
    asm volatile(
        "mma.sync.aligned.m16n8k16.row.col.f32.f16.f16.f32 "
        "{%0,%1,%2,%3}, {%4,%5,%6,%7}, {%8,%9}, {%0,%1,%2,%3};"
        : "+f"(c[0]), "+f"(c[1]), "+f"(c[2]), "+f"(c[3])
        : "r"(a[0]), "r"(a[1]), "r"(a[2]), "r"(a[3]), "r"(b0), "r"(b1));
}

__device__ __forceinline__ uint32_t h2(float lo, float hi) {
    __half2 h = __floats2half2_rn(lo, hi);
    return *(uint32_t*)&h;
}

// tile pid -> operand bases (GROUP_M=16 rasterization, unchanged)
__device__ __forceinline__ void tile_coords(int pid, int* pm, int* pn) {
    int group = pid >> 11;
    int loc = pid & 2047;
    *pm = group * 16 + (loc & 15);
    *pn = loc >> 4;
}

// ---------------- prep kernels ----------------
// cid fields: lane[0:5) s[5] it[6:9) kt[9:16) mb[16:22)
__global__ void __launch_bounds__(256)
prep_x_kernel(const float* __restrict__ X) {
    uint32_t cid = blockIdx.x * 256 + threadIdx.x;
    int lane = cid & 31;
    int s    = (cid >> 5) & 1;
    int it   = (cid >> 6) & 7;
    int kt   = (cid >> 9) & 127;
    int mb   = cid >> 16;
    int g = lane >> 2, tig = lane & 3;
    int m0 = mb * 128 + it * 16 + g;
    int k0 = kt * 32 + s * 16 + 2 * tig;
    const float* p0 = X + (size_t)m0 * K_ALL + k0;
    const float* p1 = X + (size_t)(m0 + 8) * K_ALL + k0;
    float2 v0 = *(const float2*)(p0);
    float2 v1 = *(const float2*)(p1);
    float2 v2 = *(const float2*)(p0 + 8);
    float2 v3 = *(const float2*)(p1 + 8);
    uint4 out;
    out.x = h2(v0.x, v0.y);
    out.y = h2(v1.x, v1.y);
    out.z = h2(v2.x, v2.y);
    out.w = h2(v3.x, v3.y);
    Xp[cid] = out;
}

// cid fields: lane[0:5) jt[5:9) kt[9:16) nb[16:23)
__global__ void __launch_bounds__(256)
prep_w_kernel(const float* __restrict__ W, const float* __restrict__ S) {
    uint32_t cid = blockIdx.x * 256 + threadIdx.x;
    int lane = cid & 31;
    int jt   = (cid >> 5) & 15;
    int kt   = (cid >> 9) & 127;
    int nb   = cid >> 16;
    int g = lane >> 2, tig = lane & 3;
    int n  = nb * 128 + jt * 8 + g;
    int kb = kt * 32 + 2 * tig;
    float sc = __ldg(S + (size_t)n * 32 + (kt >> 2));
    const float* p = W + (size_t)n * K_ALL + kb;
    float2 v0 = *(const float2*)(p);
    float2 v1 = *(const float2*)(p + 8);
    float2 v2 = *(const float2*)(p + 16);
    float2 v3 = *(const float2*)(p + 24);
    uint4 out;
    out.x = h2(v0.x * sc, v0.y * sc);
    out.y = h2(v1.x * sc, v1.y * sc);
    out.z = h2(v2.x * sc, v2.y * sc);
    out.w = h2(v3.x * sc, v3.y * sc);
    Wp[cid] = out;
}

// ---------------- GEMM ----------------
extern __shared__ __align__(1024) char smem_raw[];

__device__ __forceinline__ void load_tile(const uint4* __restrict__ Ablk,
                                          const uint4* __restrict__ Bblk,
                                          char* stage, int tid) {
    uint32_t sb = (uint32_t)__cvta_generic_to_shared(stage);
    #pragma unroll
    for (int i = 0; i < 4; i++)
        cp_async16(sb + (tid + i * THREADS) * 16, Ablk + tid + i * THREADS);
    #pragma unroll
    for (int i = 0; i < 4; i++)
        cp_async16(sb + (tid + (4 + i) * THREADS) * 16, Bblk + tid + i * THREADS);
}

__global__ void __launch_bounds__(THREADS, 2)
fp8linear_hmma_kernel(const float* __restrict__ BIAS,
                      float* __restrict__ OUT) {
    const int tid = threadIdx.x;
    const int lane = tid & 31;
    const int wid = tid >> 5;      // 0..3
    const int wm = wid & 1;        // 2 x 64 rows
    const int wn = wid >> 1;       // 2 x 64 cols (8 n8-tiles)
    const int g = lane >> 2;
    const int tig = lane & 3;

    // ---- load cursor (runs 3 k-steps ahead, across tiles) ----
    int ltile = blockIdx.x;
    int lkt = 0;
    int lm, ln;
    tile_coords(ltile, &lm, &ln);
    const uint4* Al = Xp + (size_t)lm * 65536;
    const uint4* Bl = Wp + (size_t)ln * 65536;

    // prologue: stages 0..2 (lkt 0..2 of first tile)
    #pragma unroll
    for (int p = 0; p < 3; p++) {
        load_tile(Al + lkt * 512, Bl + lkt * 512,
                  smem_raw + p * STAGE_BYTES, tid);
        CP_COMMIT();
        lkt++;
    }

    float acc[4][8][4];

    for (int ptile = blockIdx.x; ptile < NTILES; ptile += GRID) {
        int pid_m, pid_n;
        tile_coords(ptile, &pid_m, &pid_n);

        #pragma unroll
        for (int i = 0; i < 4; i++)
            #pragma unroll
            for (int j = 0; j < 8; j++)
                #pragma unroll
                for (int q = 0; q < 4; q++) acc[i][j][q] = 0.0f;

        for (int kt = 0; kt < NKT; kt++) {
            CP_WAIT2();
            __syncthreads();

            // produce: step kt+3 of the load stream (rolls into next tile)
            if (lkt == NKT) {
                lkt = 0;
                ltile += GRID;
                if (ltile < NTILES) {
                    tile_coords(ltile, &lm, &ln);
                    Al = Xp + (size_t)lm * 65536;
                    Bl = Wp + (size_t)ln * 65536;
                }
            }
            if (ltile < NTILES)
                load_tile(Al + lkt * 512, Bl + lkt * 512,
                          smem_raw + ((kt + 3) & 3) * STAGE_BYTES, tid);
            CP_COMMIT();
            lkt++;

            // consume stage kt&3
            const char* stg = smem_raw + (kt & 3) * STAGE_BYTES;
            const uint4* As = (const uint4*)stg;
            const uint4* Bs = (const uint4*)(stg + 8192);

            uint4 bfr[8];
            #pragma unroll
            for (int j = 0; j < 8; j++)
                bfr[j] = Bs[(wn * 8 + j) * 32 + lane];

            #pragma unroll
            for (int s = 0; s < 2; s++) {
                uint4 afr[4];
                #pragma unroll
                for (int i = 0; i < 4; i++)
                    afr[i] = As[((wm * 4 + i) * 2 + s) * 32 + lane];
                #pragma unroll
                for (int i = 0; i < 4; i++) {
                    #pragma unroll
                    for (int j = 0; j < 8; j++) {
                        uint32_t b0 = s ? bfr[j].z : bfr[j].x;
                        uint32_t b1 = s ? bfr[j].w : bfr[j].y;
                        mma_f16(acc[i][j], (const uint32_t*)&afr[i], b0, b1);
                    }
                }
            }
        }

        // ---- epilogue (overlaps next tile's in-flight prologue loads) ----
        #pragma unroll
        for (int j = 0; j < 8; j++) {
            int col = pid_n * TN + wn * 64 + j * 8 + tig * 2;
            float2 bb = *(const float2*)(BIAS + col);
            #pragma unroll
            for (int i = 0; i < 4; i++) {
                int row0 = pid_m * TM + wm * 64 + i * 16 + g;
                float2 o0, o1;
                o0.x = acc[i][j][0] + bb.x;
                o0.y = acc[i][j][1] + bb.y;
                o1.x = acc[i][j][2] + bb.x;
                o1.y = acc[i][j][3] + bb.y;
                *(float2*)(OUT + (size_t)row0 * N_ALL + col) = o0;
                *(float2*)(OUT + (size_t)(row0 + 8) * N_ALL + col) = o1;
            }
        }
    }
}

// ---------------- launch ----------------
extern "C" void kernel_launch(void* const* d_in, const int* in_sizes, int n_in,
                              void* d_out, int out_size) {
    const float* x = (const float*)d_in[0];      // [4,2048,4096]
    const float* qw = (const float*)d_in[1];     // [16384,4096]
    const float* sc = (const float*)d_in[2];     // [16384,32]
    const float* bias = (const float*)d_in[3];   // [16384]
    float* out = (float*)d_out;                  // [4,2048,16384]

    prep_x_kernel<<<4194304 / 256, 256>>>(x);
    prep_w_kernel<<<8388608 / 256, 256>>>(qw, sc);

    cudaFuncSetAttribute(fp8linear_hmma_kernel,
                         cudaFuncAttributeMaxDynamicSharedMemorySize, SMEM_TOTAL);
    fp8linear_hmma_kernel<<<GRID, THREADS, SMEM_TOTAL>>>(bias, out);
}